// round 5
// baseline (speedup 1.0000x reference)
#include <cuda_runtime.h>

#define K_CODES 16384
#define N_ROWS  8192
#define CAP     1024
#define TK      256
#define KSPLIT  8
#define KRANGE  (K_CODES / KSPLIT)   // 2048
#define PROBES  1024
#define RPW     6                    // rows per warp (sweep)
#define RPB     48                   // rows per block (8 warps * 6)
#define GRIDX   171                  // ceil(8192 / 48)

// ---------------- scratch (__device__ globals: no allocs allowed) -------------
__device__ float g_cbp[9 * K_CODES];     // SoA: j<8 -> -2*e_j[k]; j==8 -> sum e^2
__device__ float g_warm[N_ROWS];
__device__ int   g_cnt[N_ROWS];
__device__ int2  g_cand[N_ROWS * CAP];
__device__ float g_avg[K_CODES];
__device__ float g_sampleH;
__device__ float g_mse;

// ---------------- helpers -----------------------------------------------------
static __device__ __forceinline__ unsigned long long pk2(float a, float b) {
    unsigned long long r;
    asm("mov.b64 %0, {%1, %2};" : "=l"(r) : "f"(a), "f"(b));
    return r;
}
static __device__ __forceinline__ void upk2(unsigned long long v, float& a, float& b) {
    asm("mov.b64 {%0, %1}, %2;" : "=f"(a), "=f"(b) : "l"(v));
}
static __device__ __forceinline__ unsigned long long ffma2(
    unsigned long long a, unsigned long long b, unsigned long long c) {
    unsigned long long d;
    asm("fma.rn.f32x2 %0, %1, %2, %3;" : "=l"(d) : "l"(a), "l"(b), "l"(c));
    return d;
}
static __device__ __forceinline__ unsigned long long add2(
    unsigned long long a, unsigned long long b) {
    unsigned long long d;
    asm("add.rn.f32x2 %0, %1, %2;" : "=l"(d) : "l"(a), "l"(b));
    return d;
}

// ---------------- pass 0: zero scratch + preprocess codebook ------------------
__global__ void k_init(const float* __restrict__ cb) {
    int t = blockIdx.x * 256 + threadIdx.x;       // grid 64 -> t < 16384
    if (t < N_ROWS) g_cnt[t] = 0;
    if (t == 0) { g_sampleH = 0.f; g_mse = 0.f; }
    if (t < K_CODES) {
        g_avg[t] = 0.f;
        float ss = 0.f;
#pragma unroll
        for (int j = 0; j < 8; j++) {
            float e = cb[t * 8 + j];
            g_cbp[j * K_CODES + t] = -2.f * e;
            ss += e * e;
        }
        g_cbp[8 * K_CODES + t] = ss;
    }
}

// ---------------- pass 1: warm-start min over first PROBES codes --------------
// 128 blocks x 256 thr; 64 rows/block, warp w owns rows w*8..w*8+7
__global__ __launch_bounds__(256, 2) void k_warm(const float* __restrict__ z) {
    __shared__ __align__(16) float s_cb[9][2 * TK];
    __shared__ float s_z[64 * 8];

    const int tid  = threadIdx.x;
    const int lane = tid & 31;
    const int w    = tid >> 5;
    const int rowBase = blockIdx.x * 64;

    for (int i = tid; i < 512; i += 256) {
        int ro = i >> 3, j = i & 7;
        int row = rowBase + ro;
        s_z[i] = z[(row >> 8) * 2048 + j * 256 + (row & 255)];
    }
    __syncthreads();

    unsigned long long z2[4][8];
#pragma unroll
    for (int p = 0; p < 4; p++)
#pragma unroll
        for (int j = 0; j < 8; j++)
            z2[p][j] = pk2(s_z[(w * 8 + 2 * p) * 8 + j],
                           s_z[(w * 8 + 2 * p + 1) * 8 + j]);

    float dmin[8];
#pragma unroll
    for (int r = 0; r < 8; r++) dmin[r] = 3.4e38f;

    for (int tile = 0; tile < PROBES / TK; ++tile) {
        __syncthreads();
#pragma unroll
        for (int j = 0; j < 9; j++) {
            float v = g_cbp[j * K_CODES + tile * TK + tid];
            ((float2*)s_cb[j])[tid] = make_float2(v, v);
        }
        __syncthreads();
#pragma unroll 2
        for (int s = 0; s < TK / 32; s++) {
            int off = (s * 32 + lane) * 2;
            unsigned long long ee2 = *(const unsigned long long*)&s_cb[8][off];
            unsigned long long a0 = ee2, a1 = ee2, a2 = ee2, a3 = ee2;
#pragma unroll
            for (int j = 0; j < 8; j++) {
                unsigned long long ej = *(const unsigned long long*)&s_cb[j][off];
                a0 = ffma2(z2[0][j], ej, a0);
                a1 = ffma2(z2[1][j], ej, a1);
                a2 = ffma2(z2[2][j], ej, a2);
                a3 = ffma2(z2[3][j], ej, a3);
            }
            float d[8];
            upk2(a0, d[0], d[1]); upk2(a1, d[2], d[3]);
            upk2(a2, d[4], d[5]); upk2(a3, d[6], d[7]);
#pragma unroll
            for (int r = 0; r < 8; r++) dmin[r] = fminf(dmin[r], d[r]);
        }
    }
#pragma unroll
    for (int r = 0; r < 8; r++) {
        float v = dmin[r];
        for (int o = 16; o; o >>= 1)
            v = fminf(v, __shfl_xor_sync(0xffffffffu, v, o));
        if (lane == 0) g_warm[rowBase + w * 8 + r] = v;
    }
}

// ---------------- dummy launch so ncu profiles k_sweep as launch #4 -----------
__global__ void k_nop() {}

// ---------------- pass 2: single sweep, 6 rows/warp, folded-cut sign test -----
// grid (171 rowblocks, 8 ksplits) x 256 thr, 3 blocks/SM
__global__ __launch_bounds__(256, 3) void k_sweep(const float* __restrict__ z) {
    __shared__ __align__(16) float s_cb[9][2 * TK];
    __shared__ float s_z[RPB * 8];

    const int tid  = threadIdx.x;
    const int lane = tid & 31;
    const int w    = tid >> 5;
    const int rowBase = blockIdx.x * RPB;
    const int k0      = blockIdx.y * KRANGE;
    const unsigned lmask = (1u << lane) - 1u;

    // stage z rows (clamped for the partial last block)
    for (int i = tid; i < RPB * 8; i += 256) {
        int ro = i >> 3, j = i & 7;
        int row = min(rowBase + ro, N_ROWS - 1);
        s_z[i] = z[(row >> 8) * 2048 + j * 256 + (row & 255)];
    }
    __syncthreads();

    // z row-pair packs (3 pairs = 6 rows) and negated cut pairs
    unsigned long long z2[3][8], ncutp[3];
#pragma unroll
    for (int p = 0; p < 3; p++) {
#pragma unroll
        for (int j = 0; j < 8; j++)
            z2[p][j] = pk2(s_z[(w * RPW + 2 * p) * 8 + j],
                           s_z[(w * RPW + 2 * p + 1) * 8 + j]);
        int r0 = min(rowBase + w * RPW + 2 * p,     N_ROWS - 1);
        int r1 = min(rowBase + w * RPW + 2 * p + 1, N_ROWS - 1);
        // cut = warm + 0.88: exp(-100*0.88) underflows fp32 (matches ref zeros)
        ncutp[p] = pk2(-(g_warm[r0] + 0.88f), -(g_warm[r1] + 0.88f));
    }

    for (int t = 0; t < KRANGE / TK; ++t) {
        __syncthreads();
        for (int i = tid; i < 9 * TK; i += 256) {
            int j = i >> 8, c = i & 255;
            float v = g_cbp[j * K_CODES + k0 + t * TK + c];
            ((float2*)s_cb[j])[c] = make_float2(v, v);
        }
        __syncthreads();
#pragma unroll 2
        for (int s = 0; s < TK / 32; s++) {
            int off = (s * 32 + lane) * 2;
            unsigned long long ee2 = *(const unsigned long long*)&s_cb[8][off];
            unsigned long long a0 = ee2, a1 = ee2, a2 = ee2;
#pragma unroll
            for (int j = 0; j < 8; j++) {
                unsigned long long ej = *(const unsigned long long*)&s_cb[j][off];
                a0 = ffma2(z2[0][j], ej, a0);
                a1 = ffma2(z2[1][j], ej, a1);
                a2 = ffma2(z2[2][j], ej, a2);
            }
            // dshift = d - cut  (hit iff sign bit set)
            a0 = add2(a0, ncutp[0]);
            a1 = add2(a1, ncutp[1]);
            a2 = add2(a2, ncutp[2]);
            float d[6];
            upk2(a0, d[0], d[1]); upk2(a1, d[2], d[3]); upk2(a2, d[4], d[5]);
            int m = (__float_as_int(d[0]) | __float_as_int(d[1]) |
                     __float_as_int(d[2])) |
                    (__float_as_int(d[3]) | __float_as_int(d[4]) |
                     __float_as_int(d[5]));
            if (__ballot_sync(0xffffffffu, m < 0)) {   // rare, warp-uniform
                int k = k0 + t * TK + s * 32 + lane;
#pragma unroll
                for (int r = 0; r < 6; r++) {
                    unsigned bal = __ballot_sync(0xffffffffu, d[r] < 0.f);
                    int row = rowBase + w * RPW + r;
                    if (bal && row < N_ROWS) {
                        int pos = 0;
                        if (lane == 0) pos = atomicAdd(&g_cnt[row], __popc(bal));
                        pos = __shfl_sync(0xffffffffu, pos, 0);
                        if (d[r] < 0.f) {
                            int slot = pos + __popc(bal & lmask);
                            if (slot < CAP)
                                g_cand[row * CAP + slot] =
                                    make_int2(k, __float_as_int(d[r]));
                        }
                    }
                }
            }
        }
    }
}

// ---------------- pass 3: per-row finalize, online softmax (1 warp/row) -------
// note: stored d's are shifted by -cut[row] (row-uniform) -> differences exact
__global__ void k_finalize(const float* __restrict__ z,
                           const float* __restrict__ cb,
                           float* __restrict__ out) {
    int gw   = (blockIdx.x * blockDim.x + threadIdx.x) >> 5;
    int lane = threadIdx.x & 31;
    if (gw >= N_ROWS) return;

    int cnt = min(g_cnt[gw], CAP);

    float dmin = 1e30f, S1 = 0.f, S2 = 0.f;
    int   idx  = 0x7fffffff;
    for (int i = lane; i < cnt; i += 32) {
        int2 c = g_cand[gw * CAP + i];
        float d = __int_as_float(c.y);
        if (d < dmin) {
            float delta = -100.f * (dmin - d);
            float sc = __expf(delta);
            S2 = sc * (S2 + delta * S1);
            S1 = sc * S1 + 1.f;
            dmin = d; idx = c.x;
        } else {
            float arg = -100.f * (d - dmin);
            float e = __expf(arg);
            S1 += e; S2 += e * arg;
            if (d == dmin) idx = min(idx, c.x);
        }
    }
    for (int o = 16; o; o >>= 1) {
        float od  = __shfl_xor_sync(0xffffffffu, dmin, o);
        float oS1 = __shfl_xor_sync(0xffffffffu, S1, o);
        float oS2 = __shfl_xor_sync(0xffffffffu, S2, o);
        int   oix = __shfl_xor_sync(0xffffffffu, idx, o);
        float dlo = fminf(dmin, od);
        float da = -100.f * (dmin - dlo); float sa = __expf(da);
        float db = -100.f * (od  - dlo);  float sb = __expf(db);
        float nS2 = sa * (S2 + da * S1) + sb * (oS2 + db * oS1);
        float nS1 = sa * S1 + sb * oS1;
        int nidx;
        if (od < dmin)       nidx = oix;
        else if (od == dmin) nidx = min(idx, oix);
        else                 nidx = idx;
        dmin = dlo; S1 = nS1; S2 = nS2; idx = nidx;
    }

    float inv = 1.0f / (S1 * 8192.0f);
    for (int i = lane; i < cnt; i += 32) {
        int2 c = g_cand[gw * CAP + i];
        float e = __expf(-100.f * (__int_as_float(c.y) - dmin));
        if (e > 0.f) atomicAdd(&g_avg[c.x], e * inv);
    }

    int b = gw >> 8, rem = gw & 255;
    float local = 0.f;
    if (lane < 8) {
        float q  = cb[idx * 8 + lane];
        float zv = z[b * 2048 + lane * 256 + rem];
        out[b * 2048 + lane * 256 + rem] = q;
        float df = q - zv;
        local = df * df;
    }
    local += __shfl_xor_sync(0xffffffffu, local, 1);
    local += __shfl_xor_sync(0xffffffffu, local, 2);
    local += __shfl_xor_sync(0xffffffffu, local, 4);
    if (lane == 0) {
        atomicAdd(&g_mse, local);
        atomicAdd(&g_sampleH, S2 / S1 - logf(S1));
        out[65537 + gw] = (float)idx;
    }
}

// ---------------- pass 4: avg-entropy reduce + loss ---------------------------
__global__ void k_final(float* __restrict__ out) {
    __shared__ float red[256];
    float a = 0.f;
    for (int k = threadIdx.x; k < K_CODES; k += 256) {
        float av = g_avg[k];
        a += av * logf(av + 1e-5f);
    }
    red[threadIdx.x] = a;
    __syncthreads();
    for (int s = 128; s; s >>= 1) {
        if (threadIdx.x < s) red[threadIdx.x] += red[threadIdx.x + s];
        __syncthreads();
    }
    if (threadIdx.x == 0) {
        float sample_entropy = -(g_sampleH / 8192.0f);
        float ent = 0.1f * (sample_entropy + red[0]);
        out[65536] = 1.25f * g_mse / 65536.0f + ent;
    }
}

// ---------------- launch ------------------------------------------------------
extern "C" void kernel_launch(void* const* d_in, const int* in_sizes, int n_in,
                              void* d_out, int out_size) {
    const float* z  = (const float*)d_in[0];
    const float* cb = (const float*)d_in[1];
    float* out = (float*)d_out;
    (void)in_sizes; (void)n_in; (void)out_size;

    k_init<<<64, 256>>>(cb);
    k_warm<<<128, 256>>>(z);
    k_nop<<<1, 32>>>();                       // keeps k_sweep as ncu's profiled launch
    k_sweep<<<dim3(GRIDX, KSPLIT), 256>>>(z);
    k_finalize<<<N_ROWS * 32 / 256, 256>>>(z, cb, out);
    k_final<<<1, 256>>>(out);
}

// round 6
// speedup vs baseline: 1.3070x; 1.3070x over previous
#include <cuda_runtime.h>

#define K_CODES 16384
#define N_ROWS  8192
#define CAP     1024
#define TK      256            // warm-pass tile
#define TK2     512            // sweep tile
#define KSPLIT  8
#define KRANGE  (K_CODES / KSPLIT)   // 2048
#define PROBES  1024
#define RPW     4              // rows per warp (sweep)
#define RPB     32             // rows per block
#define GRIDX   (N_ROWS / RPB) // 256, exact

// ---------------- scratch (__device__ globals: no allocs allowed) -------------
__device__ float g_cbp[9 * K_CODES];              // SoA for warm pass
__device__ __align__(16) float g_cbl[4][K_CODES * 4]; // j-paired dup: {vj,vj,vj+1,vj+1}
__device__ __align__(16) float g_cblee[K_CODES * 2];  // {ee,ee}
__device__ float g_warm[N_ROWS];
__device__ int   g_cnt[N_ROWS];
__device__ int2  g_cand[N_ROWS * CAP];
__device__ float g_avg[K_CODES];
__device__ float g_sampleH;
__device__ float g_mse;

// ---------------- helpers -----------------------------------------------------
static __device__ __forceinline__ unsigned long long pk2(float a, float b) {
    unsigned long long r;
    asm("mov.b64 %0, {%1, %2};" : "=l"(r) : "f"(a), "f"(b));
    return r;
}
static __device__ __forceinline__ void upk2(unsigned long long v, float& a, float& b) {
    asm("mov.b64 {%0, %1}, %2;" : "=f"(a), "=f"(b) : "l"(v));
}
static __device__ __forceinline__ unsigned long long ffma2(
    unsigned long long a, unsigned long long b, unsigned long long c) {
    unsigned long long d;
    asm("fma.rn.f32x2 %0, %1, %2, %3;" : "=l"(d) : "l"(a), "l"(b), "l"(c));
    return d;
}
static __device__ __forceinline__ unsigned long long add2(
    unsigned long long a, unsigned long long b) {
    unsigned long long d;
    asm("add.rn.f32x2 %0, %1, %2;" : "=l"(d) : "l"(a), "l"(b));
    return d;
}

// ---------------- pass 0: zero scratch + preprocess codebook ------------------
__global__ void k_init(const float* __restrict__ cb) {
    int t = blockIdx.x * 256 + threadIdx.x;       // grid 64 -> t < 16384
    if (t < N_ROWS) g_cnt[t] = 0;
    if (t == 0) { g_sampleH = 0.f; g_mse = 0.f; }
    if (t < K_CODES) {
        g_avg[t] = 0.f;
        float v[8], ss = 0.f;
#pragma unroll
        for (int j = 0; j < 8; j++) {
            float e = cb[t * 8 + j];
            v[j] = -2.f * e;
            g_cbp[j * K_CODES + t] = v[j];
            ss += e * e;
        }
        g_cbp[8 * K_CODES + t] = ss;
#pragma unroll
        for (int a = 0; a < 4; a++) {
            g_cbl[a][t * 4 + 0] = v[2 * a];
            g_cbl[a][t * 4 + 1] = v[2 * a];
            g_cbl[a][t * 4 + 2] = v[2 * a + 1];
            g_cbl[a][t * 4 + 3] = v[2 * a + 1];
        }
        g_cblee[t * 2] = ss; g_cblee[t * 2 + 1] = ss;
    }
}

// ---------------- pass 1: warm-start min over first PROBES codes --------------
__global__ __launch_bounds__(256, 2) void k_warm(const float* __restrict__ z) {
    __shared__ __align__(16) float s_cb[9][2 * TK];
    __shared__ float s_z[64 * 8];

    const int tid  = threadIdx.x;
    const int lane = tid & 31;
    const int w    = tid >> 5;
    const int rowBase = blockIdx.x * 64;

    for (int i = tid; i < 512; i += 256) {
        int ro = i >> 3, j = i & 7;
        int row = rowBase + ro;
        s_z[i] = z[(row >> 8) * 2048 + j * 256 + (row & 255)];
    }
    __syncthreads();

    unsigned long long z2[4][8];
#pragma unroll
    for (int p = 0; p < 4; p++)
#pragma unroll
        for (int j = 0; j < 8; j++)
            z2[p][j] = pk2(s_z[(w * 8 + 2 * p) * 8 + j],
                           s_z[(w * 8 + 2 * p + 1) * 8 + j]);

    float dmin[8];
#pragma unroll
    for (int r = 0; r < 8; r++) dmin[r] = 3.4e38f;

    for (int tile = 0; tile < PROBES / TK; ++tile) {
        __syncthreads();
#pragma unroll
        for (int j = 0; j < 9; j++) {
            float v = g_cbp[j * K_CODES + tile * TK + tid];
            ((float2*)s_cb[j])[tid] = make_float2(v, v);
        }
        __syncthreads();
#pragma unroll 2
        for (int s = 0; s < TK / 32; s++) {
            int off = (s * 32 + lane) * 2;
            unsigned long long ee2 = *(const unsigned long long*)&s_cb[8][off];
            unsigned long long a0 = ee2, a1 = ee2, a2 = ee2, a3 = ee2;
#pragma unroll
            for (int j = 0; j < 8; j++) {
                unsigned long long ej = *(const unsigned long long*)&s_cb[j][off];
                a0 = ffma2(z2[0][j], ej, a0);
                a1 = ffma2(z2[1][j], ej, a1);
                a2 = ffma2(z2[2][j], ej, a2);
                a3 = ffma2(z2[3][j], ej, a3);
            }
            float d[8];
            upk2(a0, d[0], d[1]); upk2(a1, d[2], d[3]);
            upk2(a2, d[4], d[5]); upk2(a3, d[6], d[7]);
#pragma unroll
            for (int r = 0; r < 8; r++) dmin[r] = fminf(dmin[r], d[r]);
        }
    }
#pragma unroll
    for (int r = 0; r < 8; r++) {
        float v = dmin[r];
        for (int o = 16; o; o >>= 1)
            v = fminf(v, __shfl_xor_sync(0xffffffffu, v, o));
        if (lane == 0) g_warm[rowBase + w * 8 + r] = v;
    }
}

// ---------------- dummy launch so ncu profiles k_sweep as launch #4 -----------
__global__ void k_nop() {}

// ---------------- pass 2: sweep, 4 rows/warp, LDS.128 j-paired operands -------
// grid (256 rowblocks, 8 ksplits) x 256 thr, 4 blocks/SM target
__global__ __launch_bounds__(256, 4) void k_sweep(const float* __restrict__ z) {
    __shared__ __align__(16) float s_j[4][TK2 * 4];   // 8KB each
    __shared__ __align__(16) float s_ee[TK2 * 2];     // 4KB
    __shared__ float s_z[RPB * 8];

    const int tid  = threadIdx.x;
    const int lane = tid & 31;
    const int w    = tid >> 5;
    const int rowBase = blockIdx.x * RPB;
    const int k0      = blockIdx.y * KRANGE;
    const unsigned lmask = (1u << lane) - 1u;

    // stage z rows: exactly 256 elements, one per thread
    {
        int ro = tid >> 3, j = tid & 7;
        int row = rowBase + ro;
        s_z[tid] = z[(row >> 8) * 2048 + j * 256 + (row & 255)];
    }
    __syncthreads();

    // z row-pair packs (2 pairs = 4 rows) and negated cut pairs
    unsigned long long z2[2][8], ncut[2];
#pragma unroll
    for (int p = 0; p < 2; p++) {
#pragma unroll
        for (int j = 0; j < 8; j++)
            z2[p][j] = pk2(s_z[(w * RPW + 2 * p) * 8 + j],
                           s_z[(w * RPW + 2 * p + 1) * 8 + j]);
        int r0 = rowBase + w * RPW + 2 * p;
        // cut = warm + 0.88: exp(-100*0.88) underflows fp32 (matches ref zeros)
        ncut[p] = pk2(-(g_warm[r0] + 0.88f), -(g_warm[r0 + 1] + 0.88f));
    }

    for (int t = 0; t < KRANGE / TK2; ++t) {          // 4 tiles
        __syncthreads();
        // stage codebook tile: 4 arrays x 512 codes x 16B + ee 512 x 8B
        for (int i = tid; i < 4 * TK2; i += 256) {
            int a = i >> 9, c = i & (TK2 - 1);
            ((float4*)s_j[a])[c] =
                ((const float4*)g_cbl[a])[k0 + t * TK2 + c];
        }
        for (int i = tid; i < TK2; i += 256)
            ((float2*)s_ee)[i] = ((const float2*)g_cblee)[k0 + t * TK2 + i];
        __syncthreads();

#pragma unroll 2
        for (int s = 0; s < TK2 / 32; s++) {          // 16 s-iters
            int c = s * 32 + lane;
            ulonglong2 q01 = ((const ulonglong2*)s_j[0])[c];
            ulonglong2 q23 = ((const ulonglong2*)s_j[1])[c];
            ulonglong2 q45 = ((const ulonglong2*)s_j[2])[c];
            ulonglong2 q67 = ((const ulonglong2*)s_j[3])[c];
            unsigned long long ee = ((const unsigned long long*)s_ee)[c];
            unsigned long long a0 = ee, a1 = ee;
            a0 = ffma2(z2[0][0], q01.x, a0); a1 = ffma2(z2[1][0], q01.x, a1);
            a0 = ffma2(z2[0][1], q01.y, a0); a1 = ffma2(z2[1][1], q01.y, a1);
            a0 = ffma2(z2[0][2], q23.x, a0); a1 = ffma2(z2[1][2], q23.x, a1);
            a0 = ffma2(z2[0][3], q23.y, a0); a1 = ffma2(z2[1][3], q23.y, a1);
            a0 = ffma2(z2[0][4], q45.x, a0); a1 = ffma2(z2[1][4], q45.x, a1);
            a0 = ffma2(z2[0][5], q45.y, a0); a1 = ffma2(z2[1][5], q45.y, a1);
            a0 = ffma2(z2[0][6], q67.x, a0); a1 = ffma2(z2[1][6], q67.x, a1);
            a0 = ffma2(z2[0][7], q67.y, a0); a1 = ffma2(z2[1][7], q67.y, a1);
            // dshift = d - cut (hit iff sign bit set)
            a0 = add2(a0, ncut[0]);
            a1 = add2(a1, ncut[1]);
            float d[4];
            upk2(a0, d[0], d[1]); upk2(a1, d[2], d[3]);
            int m = (__float_as_int(d[0]) | __float_as_int(d[1])) |
                    (__float_as_int(d[2]) | __float_as_int(d[3]));
            if (__ballot_sync(0xffffffffu, m < 0)) {   // rare, warp-uniform
                int k = k0 + t * TK2 + c;
#pragma unroll
                for (int r = 0; r < RPW; r++) {
                    unsigned bal = __ballot_sync(0xffffffffu, d[r] < 0.f);
                    if (bal) {
                        int row = rowBase + w * RPW + r;
                        int pos = 0;
                        if (lane == 0) pos = atomicAdd(&g_cnt[row], __popc(bal));
                        pos = __shfl_sync(0xffffffffu, pos, 0);
                        if (d[r] < 0.f) {
                            int slot = pos + __popc(bal & lmask);
                            if (slot < CAP)
                                g_cand[row * CAP + slot] =
                                    make_int2(k, __float_as_int(d[r]));
                        }
                    }
                }
            }
        }
    }
}

// ---------------- pass 3: per-row finalize, online softmax (1 warp/row) -------
// note: stored d's are shifted by -cut[row] (row-uniform) -> differences exact
__global__ void k_finalize(const float* __restrict__ z,
                           const float* __restrict__ cb,
                           float* __restrict__ out) {
    int gw   = (blockIdx.x * blockDim.x + threadIdx.x) >> 5;
    int lane = threadIdx.x & 31;
    if (gw >= N_ROWS) return;

    int cnt = min(g_cnt[gw], CAP);

    float dmin = 1e30f, S1 = 0.f, S2 = 0.f;
    int   idx  = 0x7fffffff;
    for (int i = lane; i < cnt; i += 32) {
        int2 c = g_cand[gw * CAP + i];
        float d = __int_as_float(c.y);
        if (d < dmin) {
            float delta = -100.f * (dmin - d);
            float sc = __expf(delta);
            S2 = sc * (S2 + delta * S1);
            S1 = sc * S1 + 1.f;
            dmin = d; idx = c.x;
        } else {
            float arg = -100.f * (d - dmin);
            float e = __expf(arg);
            S1 += e; S2 += e * arg;
            if (d == dmin) idx = min(idx, c.x);
        }
    }
    for (int o = 16; o; o >>= 1) {
        float od  = __shfl_xor_sync(0xffffffffu, dmin, o);
        float oS1 = __shfl_xor_sync(0xffffffffu, S1, o);
        float oS2 = __shfl_xor_sync(0xffffffffu, S2, o);
        int   oix = __shfl_xor_sync(0xffffffffu, idx, o);
        float dlo = fminf(dmin, od);
        float da = -100.f * (dmin - dlo); float sa = __expf(da);
        float db = -100.f * (od  - dlo);  float sb = __expf(db);
        float nS2 = sa * (S2 + da * S1) + sb * (oS2 + db * oS1);
        float nS1 = sa * S1 + sb * oS1;
        int nidx;
        if (od < dmin)       nidx = oix;
        else if (od == dmin) nidx = min(idx, oix);
        else                 nidx = idx;
        dmin = dlo; S1 = nS1; S2 = nS2; idx = nidx;
    }

    float inv = 1.0f / (S1 * 8192.0f);
    for (int i = lane; i < cnt; i += 32) {
        int2 c = g_cand[gw * CAP + i];
        float e = __expf(-100.f * (__int_as_float(c.y) - dmin));
        if (e > 0.f) atomicAdd(&g_avg[c.x], e * inv);
    }

    int b = gw >> 8, rem = gw & 255;
    float local = 0.f;
    if (lane < 8) {
        float q  = cb[idx * 8 + lane];
        float zv = z[b * 2048 + lane * 256 + rem];
        out[b * 2048 + lane * 256 + rem] = q;
        float df = q - zv;
        local = df * df;
    }
    local += __shfl_xor_sync(0xffffffffu, local, 1);
    local += __shfl_xor_sync(0xffffffffu, local, 2);
    local += __shfl_xor_sync(0xffffffffu, local, 4);
    if (lane == 0) {
        atomicAdd(&g_mse, local);
        atomicAdd(&g_sampleH, S2 / S1 - logf(S1));
        out[65537 + gw] = (float)idx;
    }
}

// ---------------- pass 4: avg-entropy reduce + loss ---------------------------
__global__ void k_final(float* __restrict__ out) {
    __shared__ float red[256];
    float a = 0.f;
    for (int k = threadIdx.x; k < K_CODES; k += 256) {
        float av = g_avg[k];
        a += av * logf(av + 1e-5f);
    }
    red[threadIdx.x] = a;
    __syncthreads();
    for (int s = 128; s; s >>= 1) {
        if (threadIdx.x < s) red[threadIdx.x] += red[threadIdx.x + s];
        __syncthreads();
    }
    if (threadIdx.x == 0) {
        float sample_entropy = -(g_sampleH / 8192.0f);
        float ent = 0.1f * (sample_entropy + red[0]);
        out[65536] = 1.25f * g_mse / 65536.0f + ent;
    }
}

// ---------------- launch ------------------------------------------------------
extern "C" void kernel_launch(void* const* d_in, const int* in_sizes, int n_in,
                              void* d_out, int out_size) {
    const float* z  = (const float*)d_in[0];
    const float* cb = (const float*)d_in[1];
    float* out = (float*)d_out;
    (void)in_sizes; (void)n_in; (void)out_size;

    k_init<<<64, 256>>>(cb);
    k_warm<<<128, 256>>>(z);
    k_nop<<<1, 32>>>();                       // keeps k_sweep as ncu's profiled launch
    k_sweep<<<dim3(GRIDX, KSPLIT), 256>>>(z);
    k_finalize<<<N_ROWS * 32 / 256, 256>>>(z, cb, out);
    k_final<<<1, 256>>>(out);
}

// round 7
// speedup vs baseline: 1.5028x; 1.1498x over previous
#include <cuda_runtime.h>

#define K_CODES 16384
#define N_ROWS  8192
#define CAP     1024
#define TK      256            // warm-pass tile
#define PROBES  1024
#define CPB     256            // codes per block (sweep): 1 per thread
#define RSPLIT  16
#define RPB     (N_ROWS / RSPLIT)   // 512 rows per block
#define NPAIR   (RPB / 2)           // 256 row-pairs

// ---------------- scratch (__device__ globals: no allocs allowed) -------------
__device__ float g_cbp[9 * K_CODES];     // SoA: j<8 -> -2*e_j[k]; j==8 -> sum e^2
__device__ float g_warm[N_ROWS];
__device__ int   g_cnt[N_ROWS];
__device__ int2  g_cand[N_ROWS * CAP];
__device__ float g_avg[K_CODES];
__device__ float g_sampleH;
__device__ float g_mse;

// ---------------- helpers -----------------------------------------------------
static __device__ __forceinline__ unsigned long long pk2(float a, float b) {
    unsigned long long r;
    asm("mov.b64 %0, {%1, %2};" : "=l"(r) : "f"(a), "f"(b));
    return r;
}
static __device__ __forceinline__ void upk2(unsigned long long v, float& a, float& b) {
    asm("mov.b64 {%0, %1}, %2;" : "=f"(a), "=f"(b) : "l"(v));
}
static __device__ __forceinline__ unsigned long long ffma2(
    unsigned long long a, unsigned long long b, unsigned long long c) {
    unsigned long long d;
    asm("fma.rn.f32x2 %0, %1, %2, %3;" : "=l"(d) : "l"(a), "l"(b), "l"(c));
    return d;
}
static __device__ __forceinline__ unsigned long long add2(
    unsigned long long a, unsigned long long b) {
    unsigned long long d;
    asm("add.rn.f32x2 %0, %1, %2;" : "=l"(d) : "l"(a), "l"(b));
    return d;
}

// ---------------- pass 0: zero scratch + preprocess codebook ------------------
__global__ void k_init(const float* __restrict__ cb) {
    int t = blockIdx.x * 256 + threadIdx.x;       // grid 64 -> t < 16384
    if (t < N_ROWS) g_cnt[t] = 0;
    if (t == 0) { g_sampleH = 0.f; g_mse = 0.f; }
    if (t < K_CODES) {
        g_avg[t] = 0.f;
        float ss = 0.f;
#pragma unroll
        for (int j = 0; j < 8; j++) {
            float e = cb[t * 8 + j];
            g_cbp[j * K_CODES + t] = -2.f * e;
            ss += e * e;
        }
        g_cbp[8 * K_CODES + t] = ss;
    }
}

// ---------------- pass 1: warm-start min over first PROBES codes --------------
__global__ __launch_bounds__(256, 2) void k_warm(const float* __restrict__ z) {
    __shared__ __align__(16) float s_cb[9][2 * TK];
    __shared__ float s_z[64 * 8];

    const int tid  = threadIdx.x;
    const int lane = tid & 31;
    const int w    = tid >> 5;
    const int rowBase = blockIdx.x * 64;

    for (int i = tid; i < 512; i += 256) {
        int ro = i >> 3, j = i & 7;
        int row = rowBase + ro;
        s_z[i] = z[(row >> 8) * 2048 + j * 256 + (row & 255)];
    }
    __syncthreads();

    unsigned long long z2[4][8];
#pragma unroll
    for (int p = 0; p < 4; p++)
#pragma unroll
        for (int j = 0; j < 8; j++)
            z2[p][j] = pk2(s_z[(w * 8 + 2 * p) * 8 + j],
                           s_z[(w * 8 + 2 * p + 1) * 8 + j]);

    float dmin[8];
#pragma unroll
    for (int r = 0; r < 8; r++) dmin[r] = 3.4e38f;

    for (int tile = 0; tile < PROBES / TK; ++tile) {
        __syncthreads();
#pragma unroll
        for (int j = 0; j < 9; j++) {
            float v = g_cbp[j * K_CODES + tile * TK + tid];
            ((float2*)s_cb[j])[tid] = make_float2(v, v);
        }
        __syncthreads();
#pragma unroll 2
        for (int s = 0; s < TK / 32; s++) {
            int off = (s * 32 + lane) * 2;
            unsigned long long ee2 = *(const unsigned long long*)&s_cb[8][off];
            unsigned long long a0 = ee2, a1 = ee2, a2 = ee2, a3 = ee2;
#pragma unroll
            for (int j = 0; j < 8; j++) {
                unsigned long long ej = *(const unsigned long long*)&s_cb[j][off];
                a0 = ffma2(z2[0][j], ej, a0);
                a1 = ffma2(z2[1][j], ej, a1);
                a2 = ffma2(z2[2][j], ej, a2);
                a3 = ffma2(z2[3][j], ej, a3);
            }
            float d[8];
            upk2(a0, d[0], d[1]); upk2(a1, d[2], d[3]);
            upk2(a2, d[4], d[5]); upk2(a3, d[6], d[7]);
#pragma unroll
            for (int r = 0; r < 8; r++) dmin[r] = fminf(dmin[r], d[r]);
        }
    }
#pragma unroll
    for (int r = 0; r < 8; r++) {
        float v = dmin[r];
        for (int o = 16; o; o >>= 1)
            v = fminf(v, __shfl_xor_sync(0xffffffffu, v, o));
        if (lane == 0) g_warm[rowBase + w * 8 + r] = v;
    }
}

// ---------------- dummy launch so ncu profiles k_sweep as launch #4 -----------
__global__ void k_nop() {}

// ---------------- pass 2: code-resident sweep, z broadcast from smem ----------
// grid (64 codeblocks, 16 rowsplits) x 256 thr; 1 code per thread, 512 rows/blk
__global__ __launch_bounds__(256, 4) void k_sweep(const float* __restrict__ z) {
    __shared__ __align__(16) float s_zp[NPAIR * 16];            // 16KB row-pair packed
    __shared__ __align__(16) unsigned long long s_ncut[NPAIR];  // 2KB

    const int tid  = threadIdx.x;
    const int rowBase = blockIdx.y * RPB;
    const int k       = blockIdx.x * CPB + tid;   // this thread's code

    // stage z rows in row-pair layout: s_zp[rp*16 + j*2 + (row&1)]
    for (int i = tid; i < RPB * 8; i += 256) {
        int ro = i >> 3, j = i & 7;
        int row = rowBase + ro;
        s_zp[(ro >> 1) * 16 + j * 2 + (ro & 1)] =
            z[(row >> 8) * 2048 + j * 256 + (row & 255)];
    }
    // stage negated cuts per row-pair
    {
        int r0 = rowBase + 2 * tid;
        // cut = warm + 0.88: exp(-100*0.88) underflows fp32 (matches ref zeros)
        s_ncut[tid] = pk2(-(g_warm[r0] + 0.88f), -(g_warm[r0 + 1] + 0.88f));
    }

    // codebook for this code -> registers (dup-packed for f32x2)
    unsigned long long vdup[8], ee2;
#pragma unroll
    for (int j = 0; j < 8; j++) {
        float v = g_cbp[j * K_CODES + k];
        vdup[j] = pk2(v, v);
    }
    {
        float ss = g_cbp[8 * K_CODES + k];
        ee2 = pk2(ss, ss);
    }
    __syncthreads();

#pragma unroll 4
    for (int rp = 0; rp < NPAIR; rp++) {
        const ulonglong2* zp = (const ulonglong2*)&s_zp[rp * 16]; // broadcast
        ulonglong2 p0 = zp[0], p1 = zp[1], p2 = zp[2], p3 = zp[3];
        unsigned long long a = ee2;
        a = ffma2(p0.x, vdup[0], a);
        a = ffma2(p0.y, vdup[1], a);
        a = ffma2(p1.x, vdup[2], a);
        a = ffma2(p1.y, vdup[3], a);
        a = ffma2(p2.x, vdup[4], a);
        a = ffma2(p2.y, vdup[5], a);
        a = ffma2(p3.x, vdup[6], a);
        a = ffma2(p3.y, vdup[7], a);
        a = add2(a, s_ncut[rp]);               // dshift = d - cut (hit iff sign)
        float d0, d1;
        upk2(a, d0, d1);
        int m = __float_as_int(d0) | __float_as_int(d1);
        if (__ballot_sync(0xffffffffu, m < 0)) {   // rare, warp-uniform
            unsigned b0 = __ballot_sync(0xffffffffu, d0 < 0.f);
            unsigned b1 = __ballot_sync(0xffffffffu, d1 < 0.f);
            int lane = tid & 31;
            unsigned lmask = (1u << lane) - 1u;
            if (b0) {
                int row = rowBase + 2 * rp;
                int pos = 0;
                if (lane == __ffs(b0) - 1) pos = atomicAdd(&g_cnt[row], __popc(b0));
                pos = __shfl_sync(0xffffffffu, pos, __ffs(b0) - 1);
                if (d0 < 0.f) {
                    int slot = pos + __popc(b0 & lmask);
                    if (slot < CAP)
                        g_cand[row * CAP + slot] = make_int2(k, __float_as_int(d0));
                }
            }
            if (b1) {
                int row = rowBase + 2 * rp + 1;
                int pos = 0;
                if (lane == __ffs(b1) - 1) pos = atomicAdd(&g_cnt[row], __popc(b1));
                pos = __shfl_sync(0xffffffffu, pos, __ffs(b1) - 1);
                if (d1 < 0.f) {
                    int slot = pos + __popc(b1 & lmask);
                    if (slot < CAP)
                        g_cand[row * CAP + slot] = make_int2(k, __float_as_int(d1));
                }
            }
        }
    }
}

// ---------------- pass 3: per-row finalize, online softmax (1 warp/row) -------
// note: stored d's are shifted by -cut[row] (row-uniform) -> differences exact
__global__ void k_finalize(const float* __restrict__ z,
                           const float* __restrict__ cb,
                           float* __restrict__ out) {
    int gw   = (blockIdx.x * blockDim.x + threadIdx.x) >> 5;
    int lane = threadIdx.x & 31;
    if (gw >= N_ROWS) return;

    int cnt = min(g_cnt[gw], CAP);

    float dmin = 1e30f, S1 = 0.f, S2 = 0.f;
    int   idx  = 0x7fffffff;
    for (int i = lane; i < cnt; i += 32) {
        int2 c = g_cand[gw * CAP + i];
        float d = __int_as_float(c.y);
        if (d < dmin) {
            float delta = -100.f * (dmin - d);
            float sc = __expf(delta);
            S2 = sc * (S2 + delta * S1);
            S1 = sc * S1 + 1.f;
            dmin = d; idx = c.x;
        } else {
            float arg = -100.f * (d - dmin);
            float e = __expf(arg);
            S1 += e; S2 += e * arg;
            if (d == dmin) idx = min(idx, c.x);
        }
    }
    for (int o = 16; o; o >>= 1) {
        float od  = __shfl_xor_sync(0xffffffffu, dmin, o);
        float oS1 = __shfl_xor_sync(0xffffffffu, S1, o);
        float oS2 = __shfl_xor_sync(0xffffffffu, S2, o);
        int   oix = __shfl_xor_sync(0xffffffffu, idx, o);
        float dlo = fminf(dmin, od);
        float da = -100.f * (dmin - dlo); float sa = __expf(da);
        float db = -100.f * (od  - dlo);  float sb = __expf(db);
        float nS2 = sa * (S2 + da * S1) + sb * (oS2 + db * oS1);
        float nS1 = sa * S1 + sb * oS1;
        int nidx;
        if (od < dmin)       nidx = oix;
        else if (od == dmin) nidx = min(idx, oix);
        else                 nidx = idx;
        dmin = dlo; S1 = nS1; S2 = nS2; idx = nidx;
    }

    float inv = 1.0f / (S1 * 8192.0f);
    for (int i = lane; i < cnt; i += 32) {
        int2 c = g_cand[gw * CAP + i];
        float e = __expf(-100.f * (__int_as_float(c.y) - dmin));
        if (e > 0.f) atomicAdd(&g_avg[c.x], e * inv);
    }

    int b = gw >> 8, rem = gw & 255;
    float local = 0.f;
    if (lane < 8) {
        float q  = cb[idx * 8 + lane];
        float zv = z[b * 2048 + lane * 256 + rem];
        out[b * 2048 + lane * 256 + rem] = q;
        float df = q - zv;
        local = df * df;
    }
    local += __shfl_xor_sync(0xffffffffu, local, 1);
    local += __shfl_xor_sync(0xffffffffu, local, 2);
    local += __shfl_xor_sync(0xffffffffu, local, 4);
    if (lane == 0) {
        atomicAdd(&g_mse, local);
        atomicAdd(&g_sampleH, S2 / S1 - logf(S1));
        out[65537 + gw] = (float)idx;
    }
}

// ---------------- pass 4: avg-entropy reduce + loss ---------------------------
__global__ void k_final(float* __restrict__ out) {
    __shared__ float red[256];
    float a = 0.f;
    for (int k = threadIdx.x; k < K_CODES; k += 256) {
        float av = g_avg[k];
        a += av * logf(av + 1e-5f);
    }
    red[threadIdx.x] = a;
    __syncthreads();
    for (int s = 128; s; s >>= 1) {
        if (threadIdx.x < s) red[threadIdx.x] += red[threadIdx.x + s];
        __syncthreads();
    }
    if (threadIdx.x == 0) {
        float sample_entropy = -(g_sampleH / 8192.0f);
        float ent = 0.1f * (sample_entropy + red[0]);
        out[65536] = 1.25f * g_mse / 65536.0f + ent;
    }
}

// ---------------- launch ------------------------------------------------------
extern "C" void kernel_launch(void* const* d_in, const int* in_sizes, int n_in,
                              void* d_out, int out_size) {
    const float* z  = (const float*)d_in[0];
    const float* cb = (const float*)d_in[1];
    float* out = (float*)d_out;
    (void)in_sizes; (void)n_in; (void)out_size;

    k_init<<<64, 256>>>(cb);
    k_warm<<<128, 256>>>(z);
    k_nop<<<1, 32>>>();                       // keeps k_sweep as ncu's profiled launch
    k_sweep<<<dim3(K_CODES / CPB, RSPLIT), 256>>>(z);
    k_finalize<<<N_ROWS * 32 / 256, 256>>>(z, cb, out);
    k_final<<<1, 256>>>(out);
}

// round 8
// speedup vs baseline: 1.5242x; 1.0142x over previous
#include <cuda_runtime.h>

#define K_CODES 16384
#define N_ROWS  8192
#define CAP     1024
#define TK      256            // warm-pass tile
#define PROBES  1024
#define CPT     2              // codes per thread (sweep)
#define CPB     (256 * CPT)    // codes per block = 512
#define RSPLIT  16
#define RPB     (N_ROWS / RSPLIT)   // 512 rows per block
#define NPAIR   (RPB / 2)           // 256 row-pairs

// ---------------- scratch (__device__ globals: no allocs allowed) -------------
__device__ float g_cbp[9 * K_CODES];     // SoA: j<8 -> -2*e_j[k]; j==8 -> sum e^2
__device__ float g_warm[N_ROWS];
__device__ int   g_cnt[N_ROWS];
__device__ int2  g_cand[N_ROWS * CAP];
__device__ float g_avg[K_CODES];
__device__ float g_sampleH;
__device__ float g_mse;

// ---------------- helpers -----------------------------------------------------
static __device__ __forceinline__ unsigned long long pk2(float a, float b) {
    unsigned long long r;
    asm("mov.b64 %0, {%1, %2};" : "=l"(r) : "f"(a), "f"(b));
    return r;
}
static __device__ __forceinline__ void upk2(unsigned long long v, float& a, float& b) {
    asm("mov.b64 {%0, %1}, %2;" : "=f"(a), "=f"(b) : "l"(v));
}
static __device__ __forceinline__ unsigned long long ffma2(
    unsigned long long a, unsigned long long b, unsigned long long c) {
    unsigned long long d;
    asm("fma.rn.f32x2 %0, %1, %2, %3;" : "=l"(d) : "l"(a), "l"(b), "l"(c));
    return d;
}
static __device__ __forceinline__ unsigned long long add2(
    unsigned long long a, unsigned long long b) {
    unsigned long long d;
    asm("add.rn.f32x2 %0, %1, %2;" : "=l"(d) : "l"(a), "l"(b));
    return d;
}

// ---------------- pass 0: zero scratch + preprocess codebook ------------------
__global__ void k_init(const float* __restrict__ cb) {
    int t = blockIdx.x * 256 + threadIdx.x;       // grid 64 -> t < 16384
    if (t < N_ROWS) g_cnt[t] = 0;
    if (t == 0) { g_sampleH = 0.f; g_mse = 0.f; }
    if (t < K_CODES) {
        g_avg[t] = 0.f;
        float ss = 0.f;
#pragma unroll
        for (int j = 0; j < 8; j++) {
            float e = cb[t * 8 + j];
            g_cbp[j * K_CODES + t] = -2.f * e;
            ss += e * e;
        }
        g_cbp[8 * K_CODES + t] = ss;
    }
}

// ---------------- pass 1: warm-start min over first PROBES codes --------------
__global__ __launch_bounds__(256, 2) void k_warm(const float* __restrict__ z) {
    __shared__ __align__(16) float s_cb[9][2 * TK];
    __shared__ float s_z[64 * 8];

    const int tid  = threadIdx.x;
    const int lane = tid & 31;
    const int w    = tid >> 5;
    const int rowBase = blockIdx.x * 64;

    for (int i = tid; i < 512; i += 256) {
        int ro = i >> 3, j = i & 7;
        int row = rowBase + ro;
        s_z[i] = z[(row >> 8) * 2048 + j * 256 + (row & 255)];
    }
    __syncthreads();

    unsigned long long z2[4][8];
#pragma unroll
    for (int p = 0; p < 4; p++)
#pragma unroll
        for (int j = 0; j < 8; j++)
            z2[p][j] = pk2(s_z[(w * 8 + 2 * p) * 8 + j],
                           s_z[(w * 8 + 2 * p + 1) * 8 + j]);

    float dmin[8];
#pragma unroll
    for (int r = 0; r < 8; r++) dmin[r] = 3.4e38f;

    for (int tile = 0; tile < PROBES / TK; ++tile) {
        __syncthreads();
#pragma unroll
        for (int j = 0; j < 9; j++) {
            float v = g_cbp[j * K_CODES + tile * TK + tid];
            ((float2*)s_cb[j])[tid] = make_float2(v, v);
        }
        __syncthreads();
#pragma unroll 2
        for (int s = 0; s < TK / 32; s++) {
            int off = (s * 32 + lane) * 2;
            unsigned long long ee2 = *(const unsigned long long*)&s_cb[8][off];
            unsigned long long a0 = ee2, a1 = ee2, a2 = ee2, a3 = ee2;
#pragma unroll
            for (int j = 0; j < 8; j++) {
                unsigned long long ej = *(const unsigned long long*)&s_cb[j][off];
                a0 = ffma2(z2[0][j], ej, a0);
                a1 = ffma2(z2[1][j], ej, a1);
                a2 = ffma2(z2[2][j], ej, a2);
                a3 = ffma2(z2[3][j], ej, a3);
            }
            float d[8];
            upk2(a0, d[0], d[1]); upk2(a1, d[2], d[3]);
            upk2(a2, d[4], d[5]); upk2(a3, d[6], d[7]);
#pragma unroll
            for (int r = 0; r < 8; r++) dmin[r] = fminf(dmin[r], d[r]);
        }
    }
#pragma unroll
    for (int r = 0; r < 8; r++) {
        float v = dmin[r];
        for (int o = 16; o; o >>= 1)
            v = fminf(v, __shfl_xor_sync(0xffffffffu, v, o));
        if (lane == 0) g_warm[rowBase + w * 8 + r] = v;
    }
}

// ---------------- dummy launch so ncu profiles k_sweep as launch #4 -----------
__global__ void k_nop() {}

// ---------------- pass 2: code-resident sweep, 2 codes/thread, z broadcast ----
// grid (32 codeblocks, 16 rowsplits) x 256 thr; 512 rows/block
__global__ __launch_bounds__(256, 4) void k_sweep(const float* __restrict__ z) {
    __shared__ __align__(16) float s_zp[NPAIR * 16];            // 16KB row-pair packed
    __shared__ __align__(16) unsigned long long s_ncut[NPAIR];  // 2KB

    const int tid  = threadIdx.x;
    const int rowBase = blockIdx.y * RPB;
    const int kbase   = blockIdx.x * CPB + tid;   // codes: kbase, kbase+256

    // stage z rows in row-pair layout: s_zp[rp*16 + j*2 + (row&1)]
    for (int i = tid; i < RPB * 8; i += 256) {
        int ro = i >> 3, j = i & 7;
        int row = rowBase + ro;
        s_zp[(ro >> 1) * 16 + j * 2 + (ro & 1)] =
            z[(row >> 8) * 2048 + j * 256 + (row & 255)];
    }
    // stage negated cuts per row-pair
    {
        int r0 = rowBase + 2 * tid;
        // cut = warm + 0.88: exp(-100*0.88) underflows fp32 (matches ref zeros)
        s_ncut[tid] = pk2(-(g_warm[r0] + 0.88f), -(g_warm[r0 + 1] + 0.88f));
    }

    // codebooks for this thread's 2 codes -> registers (dup-packed for f32x2)
    unsigned long long vd0[8], vd1[8], ee0, ee1;
#pragma unroll
    for (int j = 0; j < 8; j++) {
        float v0 = g_cbp[j * K_CODES + kbase];
        float v1 = g_cbp[j * K_CODES + kbase + 256];
        vd0[j] = pk2(v0, v0);
        vd1[j] = pk2(v1, v1);
    }
    {
        float s0 = g_cbp[8 * K_CODES + kbase];
        float s1 = g_cbp[8 * K_CODES + kbase + 256];
        ee0 = pk2(s0, s0);
        ee1 = pk2(s1, s1);
    }
    __syncthreads();

    const int lane = tid & 31;
    const unsigned lmask = (1u << lane) - 1u;

#pragma unroll 4
    for (int rp = 0; rp < NPAIR; rp++) {
        const ulonglong2* zp = (const ulonglong2*)&s_zp[rp * 16]; // broadcast
        ulonglong2 p0 = zp[0], p1 = zp[1], p2 = zp[2], p3 = zp[3];
        unsigned long long nc = s_ncut[rp];
        unsigned long long a0 = ee0, a1 = ee1;
        a0 = ffma2(p0.x, vd0[0], a0);  a1 = ffma2(p0.x, vd1[0], a1);
        a0 = ffma2(p0.y, vd0[1], a0);  a1 = ffma2(p0.y, vd1[1], a1);
        a0 = ffma2(p1.x, vd0[2], a0);  a1 = ffma2(p1.x, vd1[2], a1);
        a0 = ffma2(p1.y, vd0[3], a0);  a1 = ffma2(p1.y, vd1[3], a1);
        a0 = ffma2(p2.x, vd0[4], a0);  a1 = ffma2(p2.x, vd1[4], a1);
        a0 = ffma2(p2.y, vd0[5], a0);  a1 = ffma2(p2.y, vd1[5], a1);
        a0 = ffma2(p3.x, vd0[6], a0);  a1 = ffma2(p3.x, vd1[6], a1);
        a0 = ffma2(p3.y, vd0[7], a0);  a1 = ffma2(p3.y, vd1[7], a1);
        a0 = add2(a0, nc);                      // dshift = d - cut (sign = hit)
        a1 = add2(a1, nc);
        float d00, d01, d10, d11;
        upk2(a0, d00, d01);
        upk2(a1, d10, d11);
        int m = (__float_as_int(d00) | __float_as_int(d01)) |
                (__float_as_int(d10) | __float_as_int(d11));
        if (__ballot_sync(0xffffffffu, m < 0)) {   // rare, warp-uniform
            unsigned b00 = __ballot_sync(0xffffffffu, d00 < 0.f);
            unsigned b01 = __ballot_sync(0xffffffffu, d01 < 0.f);
            unsigned b10 = __ballot_sync(0xffffffffu, d10 < 0.f);
            unsigned b11 = __ballot_sync(0xffffffffu, d11 < 0.f);
            int row0 = rowBase + 2 * rp, row1 = row0 + 1;
            if (b00) {
                int src = __ffs(b00) - 1, pos = 0;
                if (lane == src) pos = atomicAdd(&g_cnt[row0], __popc(b00));
                pos = __shfl_sync(0xffffffffu, pos, src);
                if (d00 < 0.f) {
                    int slot = pos + __popc(b00 & lmask);
                    if (slot < CAP)
                        g_cand[row0 * CAP + slot] = make_int2(kbase, __float_as_int(d00));
                }
            }
            if (b01) {
                int src = __ffs(b01) - 1, pos = 0;
                if (lane == src) pos = atomicAdd(&g_cnt[row1], __popc(b01));
                pos = __shfl_sync(0xffffffffu, pos, src);
                if (d01 < 0.f) {
                    int slot = pos + __popc(b01 & lmask);
                    if (slot < CAP)
                        g_cand[row1 * CAP + slot] = make_int2(kbase, __float_as_int(d01));
                }
            }
            if (b10) {
                int src = __ffs(b10) - 1, pos = 0;
                if (lane == src) pos = atomicAdd(&g_cnt[row0], __popc(b10));
                pos = __shfl_sync(0xffffffffu, pos, src);
                if (d10 < 0.f) {
                    int slot = pos + __popc(b10 & lmask);
                    if (slot < CAP)
                        g_cand[row0 * CAP + slot] = make_int2(kbase + 256, __float_as_int(d10));
                }
            }
            if (b11) {
                int src = __ffs(b11) - 1, pos = 0;
                if (lane == src) pos = atomicAdd(&g_cnt[row1], __popc(b11));
                pos = __shfl_sync(0xffffffffu, pos, src);
                if (d11 < 0.f) {
                    int slot = pos + __popc(b11 & lmask);
                    if (slot < CAP)
                        g_cand[row1 * CAP + slot] = make_int2(kbase + 256, __float_as_int(d11));
                }
            }
        }
    }
}

// ---------------- pass 3: per-row finalize, online softmax (1 warp/row) -------
// note: stored d's are shifted by -cut[row] (row-uniform) -> differences exact
__global__ void k_finalize(const float* __restrict__ z,
                           const float* __restrict__ cb,
                           float* __restrict__ out) {
    int gw   = (blockIdx.x * blockDim.x + threadIdx.x) >> 5;
    int lane = threadIdx.x & 31;
    if (gw >= N_ROWS) return;

    int cnt = min(g_cnt[gw], CAP);

    float dmin = 1e30f, S1 = 0.f, S2 = 0.f;
    int   idx  = 0x7fffffff;
    for (int i = lane; i < cnt; i += 32) {
        int2 c = g_cand[gw * CAP + i];
        float d = __int_as_float(c.y);
        if (d < dmin) {
            float delta = -100.f * (dmin - d);
            float sc = __expf(delta);
            S2 = sc * (S2 + delta * S1);
            S1 = sc * S1 + 1.f;
            dmin = d; idx = c.x;
        } else {
            float arg = -100.f * (d - dmin);
            float e = __expf(arg);
            S1 += e; S2 += e * arg;
            if (d == dmin) idx = min(idx, c.x);
        }
    }
    for (int o = 16; o; o >>= 1) {
        float od  = __shfl_xor_sync(0xffffffffu, dmin, o);
        float oS1 = __shfl_xor_sync(0xffffffffu, S1, o);
        float oS2 = __shfl_xor_sync(0xffffffffu, S2, o);
        int   oix = __shfl_xor_sync(0xffffffffu, idx, o);
        float dlo = fminf(dmin, od);
        float da = -100.f * (dmin - dlo); float sa = __expf(da);
        float db = -100.f * (od  - dlo);  float sb = __expf(db);
        float nS2 = sa * (S2 + da * S1) + sb * (oS2 + db * oS1);
        float nS1 = sa * S1 + sb * oS1;
        int nidx;
        if (od < dmin)       nidx = oix;
        else if (od == dmin) nidx = min(idx, oix);
        else                 nidx = idx;
        dmin = dlo; S1 = nS1; S2 = nS2; idx = nidx;
    }

    float inv = 1.0f / (S1 * 8192.0f);
    for (int i = lane; i < cnt; i += 32) {
        int2 c = g_cand[gw * CAP + i];
        float e = __expf(-100.f * (__int_as_float(c.y) - dmin));
        if (e > 0.f) atomicAdd(&g_avg[c.x], e * inv);
    }

    int b = gw >> 8, rem = gw & 255;
    float local = 0.f;
    if (lane < 8) {
        float q  = cb[idx * 8 + lane];
        float zv = z[b * 2048 + lane * 256 + rem];
        out[b * 2048 + lane * 256 + rem] = q;
        float df = q - zv;
        local = df * df;
    }
    local += __shfl_xor_sync(0xffffffffu, local, 1);
    local += __shfl_xor_sync(0xffffffffu, local, 2);
    local += __shfl_xor_sync(0xffffffffu, local, 4);
    if (lane == 0) {
        atomicAdd(&g_mse, local);
        atomicAdd(&g_sampleH, S2 / S1 - logf(S1));
        out[65537 + gw] = (float)idx;
    }
}

// ---------------- pass 4: avg-entropy reduce + loss ---------------------------
__global__ void k_final(float* __restrict__ out) {
    __shared__ float red[256];
    float a = 0.f;
    for (int k = threadIdx.x; k < K_CODES; k += 256) {
        float av = g_avg[k];
        a += av * logf(av + 1e-5f);
    }
    red[threadIdx.x] = a;
    __syncthreads();
    for (int s = 128; s; s >>= 1) {
        if (threadIdx.x < s) red[threadIdx.x] += red[threadIdx.x + s];
        __syncthreads();
    }
    if (threadIdx.x == 0) {
        float sample_entropy = -(g_sampleH / 8192.0f);
        float ent = 0.1f * (sample_entropy + red[0]);
        out[65536] = 1.25f * g_mse / 65536.0f + ent;
    }
}

// ---------------- launch ------------------------------------------------------
extern "C" void kernel_launch(void* const* d_in, const int* in_sizes, int n_in,
                              void* d_out, int out_size) {
    const float* z  = (const float*)d_in[0];
    const float* cb = (const float*)d_in[1];
    float* out = (float*)d_out;
    (void)in_sizes; (void)n_in; (void)out_size;

    k_init<<<64, 256>>>(cb);
    k_warm<<<128, 256>>>(z);
    k_nop<<<1, 32>>>();                       // keeps k_sweep as ncu's profiled launch
    k_sweep<<<dim3(K_CODES / CPB, RSPLIT), 256>>>(z);
    k_finalize<<<N_ROWS * 32 / 256, 256>>>(z, cb, out);
    k_final<<<1, 256>>>(out);
}

// round 9
// speedup vs baseline: 1.5428x; 1.0122x over previous
#include <cuda_runtime.h>

#define K_CODES 16384
#define N_ROWS  8192
#define CAP     1024
#define TK      256            // warm-pass tile
#define PROBES  1024
#define BT      128            // sweep block threads
#define CPT     2              // codes per thread (sweep)
#define CPB     (BT * CPT)     // codes per block = 256
#define RSPLIT  16
#define RPB     (N_ROWS / RSPLIT)   // 512 rows per block
#define NPAIR   (RPB / 2)           // 256 row-pairs

// ---------------- scratch (__device__ globals: no allocs allowed) -------------
__device__ float g_cbp[9 * K_CODES];     // SoA: j<8 -> -2*e_j[k]; j==8 -> sum e^2
__device__ float g_warm[N_ROWS];
__device__ int   g_cnt[N_ROWS];
__device__ int2  g_cand[N_ROWS * CAP];
__device__ float g_avg[K_CODES];
__device__ float g_sampleH;
__device__ float g_mse;

// ---------------- helpers -----------------------------------------------------
static __device__ __forceinline__ unsigned long long pk2(float a, float b) {
    unsigned long long r;
    asm("mov.b64 %0, {%1, %2};" : "=l"(r) : "f"(a), "f"(b));
    return r;
}
static __device__ __forceinline__ void upk2(unsigned long long v, float& a, float& b) {
    asm("mov.b64 {%0, %1}, %2;" : "=f"(a), "=f"(b) : "l"(v));
}
static __device__ __forceinline__ unsigned long long ffma2(
    unsigned long long a, unsigned long long b, unsigned long long c) {
    unsigned long long d;
    asm("fma.rn.f32x2 %0, %1, %2, %3;" : "=l"(d) : "l"(a), "l"(b), "l"(c));
    return d;
}
static __device__ __forceinline__ unsigned long long add2(
    unsigned long long a, unsigned long long b) {
    unsigned long long d;
    asm("add.rn.f32x2 %0, %1, %2;" : "=l"(d) : "l"(a), "l"(b));
    return d;
}

// ---------------- pass 0: zero scratch + preprocess codebook ------------------
__global__ void k_init(const float* __restrict__ cb) {
    int t = blockIdx.x * 256 + threadIdx.x;       // grid 64 -> t < 16384
    if (t < N_ROWS) g_cnt[t] = 0;
    if (t == 0) { g_sampleH = 0.f; g_mse = 0.f; }
    if (t < K_CODES) {
        g_avg[t] = 0.f;
        float ss = 0.f;
#pragma unroll
        for (int j = 0; j < 8; j++) {
            float e = cb[t * 8 + j];
            g_cbp[j * K_CODES + t] = -2.f * e;
            ss += e * e;
        }
        g_cbp[8 * K_CODES + t] = ss;
    }
}

// ---------------- pass 1: warm-start min over first PROBES codes --------------
__global__ __launch_bounds__(256, 2) void k_warm(const float* __restrict__ z) {
    __shared__ __align__(16) float s_cb[9][2 * TK];
    __shared__ float s_z[64 * 8];

    const int tid  = threadIdx.x;
    const int lane = tid & 31;
    const int w    = tid >> 5;
    const int rowBase = blockIdx.x * 64;

    for (int i = tid; i < 512; i += 256) {
        int ro = i >> 3, j = i & 7;
        int row = rowBase + ro;
        s_z[i] = z[(row >> 8) * 2048 + j * 256 + (row & 255)];
    }
    __syncthreads();

    unsigned long long z2[4][8];
#pragma unroll
    for (int p = 0; p < 4; p++)
#pragma unroll
        for (int j = 0; j < 8; j++)
            z2[p][j] = pk2(s_z[(w * 8 + 2 * p) * 8 + j],
                           s_z[(w * 8 + 2 * p + 1) * 8 + j]);

    float dmin[8];
#pragma unroll
    for (int r = 0; r < 8; r++) dmin[r] = 3.4e38f;

    for (int tile = 0; tile < PROBES / TK; ++tile) {
        __syncthreads();
#pragma unroll
        for (int j = 0; j < 9; j++) {
            float v = g_cbp[j * K_CODES + tile * TK + tid];
            ((float2*)s_cb[j])[tid] = make_float2(v, v);
        }
        __syncthreads();
#pragma unroll 2
        for (int s = 0; s < TK / 32; s++) {
            int off = (s * 32 + lane) * 2;
            unsigned long long ee2 = *(const unsigned long long*)&s_cb[8][off];
            unsigned long long a0 = ee2, a1 = ee2, a2 = ee2, a3 = ee2;
#pragma unroll
            for (int j = 0; j < 8; j++) {
                unsigned long long ej = *(const unsigned long long*)&s_cb[j][off];
                a0 = ffma2(z2[0][j], ej, a0);
                a1 = ffma2(z2[1][j], ej, a1);
                a2 = ffma2(z2[2][j], ej, a2);
                a3 = ffma2(z2[3][j], ej, a3);
            }
            float d[8];
            upk2(a0, d[0], d[1]); upk2(a1, d[2], d[3]);
            upk2(a2, d[4], d[5]); upk2(a3, d[6], d[7]);
#pragma unroll
            for (int r = 0; r < 8; r++) dmin[r] = fminf(dmin[r], d[r]);
        }
    }
#pragma unroll
    for (int r = 0; r < 8; r++) {
        float v = dmin[r];
        for (int o = 16; o; o >>= 1)
            v = fminf(v, __shfl_xor_sync(0xffffffffu, v, o));
        if (lane == 0) g_warm[rowBase + w * 8 + r] = v;
    }
}

// ---------------- dummy launch so ncu profiles k_sweep as launch #4 -----------
__global__ void k_nop() {}

// ---------------- pass 2: code-resident sweep, 2 codes/thread, z broadcast ----
// grid (64 codeblocks, 16 rowsplits) x 128 thr; 8 blocks/SM for fine balance
__global__ __launch_bounds__(BT, 8) void k_sweep(const float* __restrict__ z) {
    __shared__ __align__(16) float s_zp[NPAIR * 16];            // 16KB row-pair packed
    __shared__ __align__(16) unsigned long long s_ncut[NPAIR];  // 2KB

    const int tid  = threadIdx.x;
    const int rowBase = blockIdx.y * RPB;
    const int kbase   = blockIdx.x * CPB + tid;   // codes: kbase, kbase+BT

    // stage z rows in row-pair layout: s_zp[rp*16 + j*2 + (row&1)]
    for (int i = tid; i < RPB * 8; i += BT) {
        int ro = i >> 3, j = i & 7;
        int row = rowBase + ro;
        s_zp[(ro >> 1) * 16 + j * 2 + (ro & 1)] =
            z[(row >> 8) * 2048 + j * 256 + (row & 255)];
    }
    // stage negated cuts per row-pair (2 per thread)
#pragma unroll
    for (int u = 0; u < NPAIR / BT; u++) {
        int rp = u * BT + tid;
        int r0 = rowBase + 2 * rp;
        // cut = warm + 0.88: exp(-100*0.88) underflows fp32 (matches ref zeros)
        s_ncut[rp] = pk2(-(g_warm[r0] + 0.88f), -(g_warm[r0 + 1] + 0.88f));
    }

    // codebooks for this thread's 2 codes -> registers (dup-packed for f32x2)
    unsigned long long vd0[8], vd1[8], ee0, ee1;
#pragma unroll
    for (int j = 0; j < 8; j++) {
        float v0 = g_cbp[j * K_CODES + kbase];
        float v1 = g_cbp[j * K_CODES + kbase + BT];
        vd0[j] = pk2(v0, v0);
        vd1[j] = pk2(v1, v1);
    }
    {
        float s0 = g_cbp[8 * K_CODES + kbase];
        float s1 = g_cbp[8 * K_CODES + kbase + BT];
        ee0 = pk2(s0, s0);
        ee1 = pk2(s1, s1);
    }
    __syncthreads();

    const int lane = tid & 31;
    const unsigned lmask = (1u << lane) - 1u;

#pragma unroll 8
    for (int rp = 0; rp < NPAIR; rp++) {
        const ulonglong2* zp = (const ulonglong2*)&s_zp[rp * 16]; // broadcast
        ulonglong2 p0 = zp[0], p1 = zp[1], p2 = zp[2], p3 = zp[3];
        unsigned long long nc = s_ncut[rp];
        unsigned long long a0 = ee0, a1 = ee1;
        a0 = ffma2(p0.x, vd0[0], a0);  a1 = ffma2(p0.x, vd1[0], a1);
        a0 = ffma2(p0.y, vd0[1], a0);  a1 = ffma2(p0.y, vd1[1], a1);
        a0 = ffma2(p1.x, vd0[2], a0);  a1 = ffma2(p1.x, vd1[2], a1);
        a0 = ffma2(p1.y, vd0[3], a0);  a1 = ffma2(p1.y, vd1[3], a1);
        a0 = ffma2(p2.x, vd0[4], a0);  a1 = ffma2(p2.x, vd1[4], a1);
        a0 = ffma2(p2.y, vd0[5], a0);  a1 = ffma2(p2.y, vd1[5], a1);
        a0 = ffma2(p3.x, vd0[6], a0);  a1 = ffma2(p3.x, vd1[6], a1);
        a0 = ffma2(p3.y, vd0[7], a0);  a1 = ffma2(p3.y, vd1[7], a1);
        a0 = add2(a0, nc);                      // dshift = d - cut (sign = hit)
        a1 = add2(a1, nc);
        float d00, d01, d10, d11;
        upk2(a0, d00, d01);
        upk2(a1, d10, d11);
        int m = (__float_as_int(d00) | __float_as_int(d01)) |
                (__float_as_int(d10) | __float_as_int(d11));
        if (__ballot_sync(0xffffffffu, m < 0)) {   // rare, warp-uniform
            unsigned b00 = __ballot_sync(0xffffffffu, d00 < 0.f);
            unsigned b01 = __ballot_sync(0xffffffffu, d01 < 0.f);
            unsigned b10 = __ballot_sync(0xffffffffu, d10 < 0.f);
            unsigned b11 = __ballot_sync(0xffffffffu, d11 < 0.f);
            int row0 = rowBase + 2 * rp, row1 = row0 + 1;
            if (b00) {
                int src = __ffs(b00) - 1, pos = 0;
                if (lane == src) pos = atomicAdd(&g_cnt[row0], __popc(b00));
                pos = __shfl_sync(0xffffffffu, pos, src);
                if (d00 < 0.f) {
                    int slot = pos + __popc(b00 & lmask);
                    if (slot < CAP)
                        g_cand[row0 * CAP + slot] = make_int2(kbase, __float_as_int(d00));
                }
            }
            if (b01) {
                int src = __ffs(b01) - 1, pos = 0;
                if (lane == src) pos = atomicAdd(&g_cnt[row1], __popc(b01));
                pos = __shfl_sync(0xffffffffu, pos, src);
                if (d01 < 0.f) {
                    int slot = pos + __popc(b01 & lmask);
                    if (slot < CAP)
                        g_cand[row1 * CAP + slot] = make_int2(kbase, __float_as_int(d01));
                }
            }
            if (b10) {
                int src = __ffs(b10) - 1, pos = 0;
                if (lane == src) pos = atomicAdd(&g_cnt[row0], __popc(b10));
                pos = __shfl_sync(0xffffffffu, pos, src);
                if (d10 < 0.f) {
                    int slot = pos + __popc(b10 & lmask);
                    if (slot < CAP)
                        g_cand[row0 * CAP + slot] = make_int2(kbase + BT, __float_as_int(d10));
                }
            }
            if (b11) {
                int src = __ffs(b11) - 1, pos = 0;
                if (lane == src) pos = atomicAdd(&g_cnt[row1], __popc(b11));
                pos = __shfl_sync(0xffffffffu, pos, src);
                if (d11 < 0.f) {
                    int slot = pos + __popc(b11 & lmask);
                    if (slot < CAP)
                        g_cand[row1 * CAP + slot] = make_int2(kbase + BT, __float_as_int(d11));
                }
            }
        }
    }
}

// ---------------- pass 3: per-row finalize, online softmax (1 warp/row) -------
// note: stored d's are shifted by -cut[row] (row-uniform) -> differences exact
__global__ void k_finalize(const float* __restrict__ z,
                           const float* __restrict__ cb,
                           float* __restrict__ out) {
    int gw   = (blockIdx.x * blockDim.x + threadIdx.x) >> 5;
    int lane = threadIdx.x & 31;
    if (gw >= N_ROWS) return;

    int cnt = min(g_cnt[gw], CAP);

    float dmin = 1e30f, S1 = 0.f, S2 = 0.f;
    int   idx  = 0x7fffffff;
    for (int i = lane; i < cnt; i += 32) {
        int2 c = g_cand[gw * CAP + i];
        float d = __int_as_float(c.y);
        if (d < dmin) {
            float delta = -100.f * (dmin - d);
            float sc = __expf(delta);
            S2 = sc * (S2 + delta * S1);
            S1 = sc * S1 + 1.f;
            dmin = d; idx = c.x;
        } else {
            float arg = -100.f * (d - dmin);
            float e = __expf(arg);
            S1 += e; S2 += e * arg;
            if (d == dmin) idx = min(idx, c.x);
        }
    }
    for (int o = 16; o; o >>= 1) {
        float od  = __shfl_xor_sync(0xffffffffu, dmin, o);
        float oS1 = __shfl_xor_sync(0xffffffffu, S1, o);
        float oS2 = __shfl_xor_sync(0xffffffffu, S2, o);
        int   oix = __shfl_xor_sync(0xffffffffu, idx, o);
        float dlo = fminf(dmin, od);
        float da = -100.f * (dmin - dlo); float sa = __expf(da);
        float db = -100.f * (od  - dlo);  float sb = __expf(db);
        float nS2 = sa * (S2 + da * S1) + sb * (oS2 + db * oS1);
        float nS1 = sa * S1 + sb * oS1;
        int nidx;
        if (od < dmin)       nidx = oix;
        else if (od == dmin) nidx = min(idx, oix);
        else                 nidx = idx;
        dmin = dlo; S1 = nS1; S2 = nS2; idx = nidx;
    }

    float inv = 1.0f / (S1 * 8192.0f);
    for (int i = lane; i < cnt; i += 32) {
        int2 c = g_cand[gw * CAP + i];
        float e = __expf(-100.f * (__int_as_float(c.y) - dmin));
        if (e > 0.f) atomicAdd(&g_avg[c.x], e * inv);
    }

    int b = gw >> 8, rem = gw & 255;
    float local = 0.f;
    if (lane < 8) {
        float q  = cb[idx * 8 + lane];
        float zv = z[b * 2048 + lane * 256 + rem];
        out[b * 2048 + lane * 256 + rem] = q;
        float df = q - zv;
        local = df * df;
    }
    local += __shfl_xor_sync(0xffffffffu, local, 1);
    local += __shfl_xor_sync(0xffffffffu, local, 2);
    local += __shfl_xor_sync(0xffffffffu, local, 4);
    if (lane == 0) {
        atomicAdd(&g_mse, local);
        atomicAdd(&g_sampleH, S2 / S1 - logf(S1));
        out[65537 + gw] = (float)idx;
    }
}

// ---------------- pass 4: avg-entropy reduce + loss ---------------------------
__global__ void k_final(float* __restrict__ out) {
    __shared__ float red[256];
    float a = 0.f;
    for (int k = threadIdx.x; k < K_CODES; k += 256) {
        float av = g_avg[k];
        a += av * logf(av + 1e-5f);
    }
    red[threadIdx.x] = a;
    __syncthreads();
    for (int s = 128; s; s >>= 1) {
        if (threadIdx.x < s) red[threadIdx.x] += red[threadIdx.x + s];
        __syncthreads();
    }
    if (threadIdx.x == 0) {
        float sample_entropy = -(g_sampleH / 8192.0f);
        float ent = 0.1f * (sample_entropy + red[0]);
        out[65536] = 1.25f * g_mse / 65536.0f + ent;
    }
}

// ---------------- launch ------------------------------------------------------
extern "C" void kernel_launch(void* const* d_in, const int* in_sizes, int n_in,
                              void* d_out, int out_size) {
    const float* z  = (const float*)d_in[0];
    const float* cb = (const float*)d_in[1];
    float* out = (float*)d_out;
    (void)in_sizes; (void)n_in; (void)out_size;

    k_init<<<64, 256>>>(cb);
    k_warm<<<128, 256>>>(z);
    k_nop<<<1, 32>>>();                       // keeps k_sweep as ncu's profiled launch
    k_sweep<<<dim3(K_CODES / CPB, RSPLIT), BT>>>(z);
    k_finalize<<<N_ROWS * 32 / 256, 256>>>(z, cb, out);
    k_final<<<1, 256>>>(out);
}

// round 10
// speedup vs baseline: 1.6221x; 1.0514x over previous
#include <cuda_runtime.h>

#define K_CODES 16384
#define N_ROWS  8192
#define CAP     1024
#define TK      256            // warm-pass tile
#define PROBES  1024
#define BT      128            // sweep block threads
#define CPT     2              // codes per thread (sweep)
#define CPB     (BT * CPT)     // codes per block = 256
#define RSPLIT  16
#define RPB     (N_ROWS / RSPLIT)   // 512 rows per block
#define NPAIR   (RPB / 2)           // 256 row-pairs
#define GRP     4                   // rp-group size for hit check

// ---------------- scratch (__device__ globals: no allocs allowed) -------------
__device__ float g_cbp[9 * K_CODES];     // SoA: j<8 -> -2*e_j[k]; j==8 -> sum e^2
__device__ float g_warm[N_ROWS];
__device__ int   g_cnt[N_ROWS];
__device__ int2  g_cand[N_ROWS * CAP];
__device__ float g_avg[K_CODES];
__device__ float g_sampleH;
__device__ float g_mse;

// ---------------- helpers -----------------------------------------------------
static __device__ __forceinline__ unsigned long long pk2(float a, float b) {
    unsigned long long r;
    asm("mov.b64 %0, {%1, %2};" : "=l"(r) : "f"(a), "f"(b));
    return r;
}
static __device__ __forceinline__ void upk2(unsigned long long v, float& a, float& b) {
    asm("mov.b64 {%0, %1}, %2;" : "=f"(a), "=f"(b) : "l"(v));
}
static __device__ __forceinline__ unsigned long long ffma2(
    unsigned long long a, unsigned long long b, unsigned long long c) {
    unsigned long long d;
    asm("fma.rn.f32x2 %0, %1, %2, %3;" : "=l"(d) : "l"(a), "l"(b), "l"(c));
    return d;
}
static __device__ __forceinline__ unsigned long long add2(
    unsigned long long a, unsigned long long b) {
    unsigned long long d;
    asm("add.rn.f32x2 %0, %1, %2;" : "=l"(d) : "l"(a), "l"(b));
    return d;
}
static __device__ __forceinline__ unsigned hi32(unsigned long long v) {
    return (unsigned)(v >> 32);
}
static __device__ __forceinline__ unsigned lo32(unsigned long long v) {
    return (unsigned)v;
}

// ---------------- pass 0: zero scratch + preprocess codebook ------------------
__global__ void k_init(const float* __restrict__ cb) {
    int t = blockIdx.x * 256 + threadIdx.x;       // grid 64 -> t < 16384
    if (t < N_ROWS) g_cnt[t] = 0;
    if (t == 0) { g_sampleH = 0.f; g_mse = 0.f; }
    if (t < K_CODES) {
        g_avg[t] = 0.f;
        float ss = 0.f;
#pragma unroll
        for (int j = 0; j < 8; j++) {
            float e = cb[t * 8 + j];
            g_cbp[j * K_CODES + t] = -2.f * e;
            ss += e * e;
        }
        g_cbp[8 * K_CODES + t] = ss;
    }
}

// ---------------- pass 1: warm-start min over first PROBES codes --------------
__global__ __launch_bounds__(256, 2) void k_warm(const float* __restrict__ z) {
    __shared__ __align__(16) float s_cb[9][2 * TK];
    __shared__ float s_z[64 * 8];

    const int tid  = threadIdx.x;
    const int lane = tid & 31;
    const int w    = tid >> 5;
    const int rowBase = blockIdx.x * 64;

    for (int i = tid; i < 512; i += 256) {
        int ro = i >> 3, j = i & 7;
        int row = rowBase + ro;
        s_z[i] = z[(row >> 8) * 2048 + j * 256 + (row & 255)];
    }
    __syncthreads();

    unsigned long long z2[4][8];
#pragma unroll
    for (int p = 0; p < 4; p++)
#pragma unroll
        for (int j = 0; j < 8; j++)
            z2[p][j] = pk2(s_z[(w * 8 + 2 * p) * 8 + j],
                           s_z[(w * 8 + 2 * p + 1) * 8 + j]);

    float dmin[8];
#pragma unroll
    for (int r = 0; r < 8; r++) dmin[r] = 3.4e38f;

    for (int tile = 0; tile < PROBES / TK; ++tile) {
        __syncthreads();
#pragma unroll
        for (int j = 0; j < 9; j++) {
            float v = g_cbp[j * K_CODES + tile * TK + tid];
            ((float2*)s_cb[j])[tid] = make_float2(v, v);
        }
        __syncthreads();
#pragma unroll 2
        for (int s = 0; s < TK / 32; s++) {
            int off = (s * 32 + lane) * 2;
            unsigned long long ee2 = *(const unsigned long long*)&s_cb[8][off];
            unsigned long long a0 = ee2, a1 = ee2, a2 = ee2, a3 = ee2;
#pragma unroll
            for (int j = 0; j < 8; j++) {
                unsigned long long ej = *(const unsigned long long*)&s_cb[j][off];
                a0 = ffma2(z2[0][j], ej, a0);
                a1 = ffma2(z2[1][j], ej, a1);
                a2 = ffma2(z2[2][j], ej, a2);
                a3 = ffma2(z2[3][j], ej, a3);
            }
            float d[8];
            upk2(a0, d[0], d[1]); upk2(a1, d[2], d[3]);
            upk2(a2, d[4], d[5]); upk2(a3, d[6], d[7]);
#pragma unroll
            for (int r = 0; r < 8; r++) dmin[r] = fminf(dmin[r], d[r]);
        }
    }
#pragma unroll
    for (int r = 0; r < 8; r++) {
        float v = dmin[r];
        for (int o = 16; o; o >>= 1)
            v = fminf(v, __shfl_xor_sync(0xffffffffu, v, o));
        if (lane == 0) g_warm[rowBase + w * 8 + r] = v;
    }
}

// ---------------- dummy launch so ncu profiles k_sweep as launch #4 -----------
__global__ void k_nop() {}

// ---------------- pass 2: code-resident sweep, grouped sign-check -------------
// grid (64 codeblocks, 16 rowsplits) x 128 thr
__global__ __launch_bounds__(BT, 8) void k_sweep(const float* __restrict__ z) {
    __shared__ __align__(16) float s_zp[NPAIR * 16];            // 16KB row-pair packed
    __shared__ __align__(16) unsigned long long s_ncut[NPAIR];  // 2KB

    const int tid  = threadIdx.x;
    const int rowBase = blockIdx.y * RPB;
    const int kbase   = blockIdx.x * CPB + tid;   // codes: kbase, kbase+BT

    // stage z rows, coalesced: j outer, consecutive rows inner
#pragma unroll
    for (int i = 0; i < 32; i++) {                // 8 j x 4 row-chunks
        int j  = i >> 2;
        int ro = (i & 3) * BT + tid;
        int row = rowBase + ro;
        s_zp[(ro >> 1) * 16 + j * 2 + (ro & 1)] =
            z[(row >> 8) * 2048 + j * 256 + (row & 255)];
    }
    // stage negated cuts per row-pair (2 per thread)
#pragma unroll
    for (int u = 0; u < NPAIR / BT; u++) {
        int rp = u * BT + tid;
        int r0 = rowBase + 2 * rp;
        // cut = warm + 0.88: exp(-100*0.88) underflows fp32 (matches ref zeros)
        s_ncut[rp] = pk2(-(g_warm[r0] + 0.88f), -(g_warm[r0 + 1] + 0.88f));
    }

    // codebooks for this thread's 2 codes -> registers (dup-packed for f32x2)
    unsigned long long vd0[8], vd1[8], ee0, ee1;
#pragma unroll
    for (int j = 0; j < 8; j++) {
        float v0 = g_cbp[j * K_CODES + kbase];
        float v1 = g_cbp[j * K_CODES + kbase + BT];
        vd0[j] = pk2(v0, v0);
        vd1[j] = pk2(v1, v1);
    }
    {
        float s0 = g_cbp[8 * K_CODES + kbase];
        float s1 = g_cbp[8 * K_CODES + kbase + BT];
        ee0 = pk2(s0, s0);
        ee1 = pk2(s1, s1);
    }
    __syncthreads();

#pragma unroll 2
    for (int g = 0; g < NPAIR / GRP; g++) {
        unsigned acc = 0;
        // ---- fast pass: signs only, no unpack / compare / vote / branch -----
#pragma unroll
        for (int u = 0; u < GRP; u++) {
            int rp = g * GRP + u;
            const ulonglong2* zp = (const ulonglong2*)&s_zp[rp * 16]; // broadcast
            ulonglong2 p0 = zp[0], p1 = zp[1], p2 = zp[2], p3 = zp[3];
            unsigned long long a0 = add2(ee0, s_ncut[rp]);
            unsigned long long a1 = add2(ee1, s_ncut[rp]);
            a0 = ffma2(p0.x, vd0[0], a0);  a1 = ffma2(p0.x, vd1[0], a1);
            a0 = ffma2(p0.y, vd0[1], a0);  a1 = ffma2(p0.y, vd1[1], a1);
            a0 = ffma2(p1.x, vd0[2], a0);  a1 = ffma2(p1.x, vd1[2], a1);
            a0 = ffma2(p1.y, vd0[3], a0);  a1 = ffma2(p1.y, vd1[3], a1);
            a0 = ffma2(p2.x, vd0[4], a0);  a1 = ffma2(p2.x, vd1[4], a1);
            a0 = ffma2(p2.y, vd0[5], a0);  a1 = ffma2(p2.y, vd1[5], a1);
            a0 = ffma2(p3.x, vd0[6], a0);  a1 = ffma2(p3.x, vd1[6], a1);
            a0 = ffma2(p3.y, vd0[7], a0);  a1 = ffma2(p3.y, vd1[7], a1);
            acc |= (lo32(a0) | hi32(a0)) | (lo32(a1) | hi32(a1));
        }
        // ---- rare slow pass: bit-identical recompute + per-lane atomics -----
        if ((int)acc < 0) {
#pragma unroll
            for (int u = 0; u < GRP; u++) {
                int rp = g * GRP + u;
                const ulonglong2* zp = (const ulonglong2*)&s_zp[rp * 16];
                ulonglong2 p0 = zp[0], p1 = zp[1], p2 = zp[2], p3 = zp[3];
                unsigned long long a0 = add2(ee0, s_ncut[rp]);
                unsigned long long a1 = add2(ee1, s_ncut[rp]);
                a0 = ffma2(p0.x, vd0[0], a0);  a1 = ffma2(p0.x, vd1[0], a1);
                a0 = ffma2(p0.y, vd0[1], a0);  a1 = ffma2(p0.y, vd1[1], a1);
                a0 = ffma2(p1.x, vd0[2], a0);  a1 = ffma2(p1.x, vd1[2], a1);
                a0 = ffma2(p1.y, vd0[3], a0);  a1 = ffma2(p1.y, vd1[3], a1);
                a0 = ffma2(p2.x, vd0[4], a0);  a1 = ffma2(p2.x, vd1[4], a1);
                a0 = ffma2(p2.y, vd0[5], a0);  a1 = ffma2(p2.y, vd1[5], a1);
                a0 = ffma2(p3.x, vd0[6], a0);  a1 = ffma2(p3.x, vd1[6], a1);
                a0 = ffma2(p3.y, vd0[7], a0);  a1 = ffma2(p3.y, vd1[7], a1);
                float d00, d01, d10, d11;
                upk2(a0, d00, d01);
                upk2(a1, d10, d11);
                int row0 = rowBase + 2 * rp, row1 = row0 + 1;
                if (d00 < 0.f) {
                    int pos = atomicAdd(&g_cnt[row0], 1);
                    if (pos < CAP)
                        g_cand[row0 * CAP + pos] = make_int2(kbase, __float_as_int(d00));
                }
                if (d01 < 0.f) {
                    int pos = atomicAdd(&g_cnt[row1], 1);
                    if (pos < CAP)
                        g_cand[row1 * CAP + pos] = make_int2(kbase, __float_as_int(d01));
                }
                if (d10 < 0.f) {
                    int pos = atomicAdd(&g_cnt[row0], 1);
                    if (pos < CAP)
                        g_cand[row0 * CAP + pos] = make_int2(kbase + BT, __float_as_int(d10));
                }
                if (d11 < 0.f) {
                    int pos = atomicAdd(&g_cnt[row1], 1);
                    if (pos < CAP)
                        g_cand[row1 * CAP + pos] = make_int2(kbase + BT, __float_as_int(d11));
                }
            }
        }
    }
}

// ---------------- pass 3: per-row finalize, online softmax (1 warp/row) -------
// note: stored d's are shifted by -cut[row] (row-uniform) -> differences exact
__global__ void k_finalize(const float* __restrict__ z,
                           const float* __restrict__ cb,
                           float* __restrict__ out) {
    int gw   = (blockIdx.x * blockDim.x + threadIdx.x) >> 5;
    int lane = threadIdx.x & 31;
    if (gw >= N_ROWS) return;

    int cnt = min(g_cnt[gw], CAP);

    float dmin = 1e30f, S1 = 0.f, S2 = 0.f;
    int   idx  = 0x7fffffff;
    for (int i = lane; i < cnt; i += 32) {
        int2 c = g_cand[gw * CAP + i];
        float d = __int_as_float(c.y);
        if (d < dmin) {
            float delta = -100.f * (dmin - d);
            float sc = __expf(delta);
            S2 = sc * (S2 + delta * S1);
            S1 = sc * S1 + 1.f;
            dmin = d; idx = c.x;
        } else {
            float arg = -100.f * (d - dmin);
            float e = __expf(arg);
            S1 += e; S2 += e * arg;
            if (d == dmin) idx = min(idx, c.x);
        }
    }
    for (int o = 16; o; o >>= 1) {
        float od  = __shfl_xor_sync(0xffffffffu, dmin, o);
        float oS1 = __shfl_xor_sync(0xffffffffu, S1, o);
        float oS2 = __shfl_xor_sync(0xffffffffu, S2, o);
        int   oix = __shfl_xor_sync(0xffffffffu, idx, o);
        float dlo = fminf(dmin, od);
        float da = -100.f * (dmin - dlo); float sa = __expf(da);
        float db = -100.f * (od  - dlo);  float sb = __expf(db);
        float nS2 = sa * (S2 + da * S1) + sb * (oS2 + db * oS1);
        float nS1 = sa * S1 + sb * oS1;
        int nidx;
        if (od < dmin)       nidx = oix;
        else if (od == dmin) nidx = min(idx, oix);
        else                 nidx = idx;
        dmin = dlo; S1 = nS1; S2 = nS2; idx = nidx;
    }

    float inv = 1.0f / (S1 * 8192.0f);
    for (int i = lane; i < cnt; i += 32) {
        int2 c = g_cand[gw * CAP + i];
        float e = __expf(-100.f * (__int_as_float(c.y) - dmin));
        if (e > 0.f) atomicAdd(&g_avg[c.x], e * inv);
    }

    int b = gw >> 8, rem = gw & 255;
    float local = 0.f;
    if (lane < 8) {
        float q  = cb[idx * 8 + lane];
        float zv = z[b * 2048 + lane * 256 + rem];
        out[b * 2048 + lane * 256 + rem] = q;
        float df = q - zv;
        local = df * df;
    }
    local += __shfl_xor_sync(0xffffffffu, local, 1);
    local += __shfl_xor_sync(0xffffffffu, local, 2);
    local += __shfl_xor_sync(0xffffffffu, local, 4);
    if (lane == 0) {
        atomicAdd(&g_mse, local);
        atomicAdd(&g_sampleH, S2 / S1 - logf(S1));
        out[65537 + gw] = (float)idx;
    }
}

// ---------------- pass 4: avg-entropy reduce + loss ---------------------------
__global__ void k_final(float* __restrict__ out) {
    __shared__ float red[256];
    float a = 0.f;
    for (int k = threadIdx.x; k < K_CODES; k += 256) {
        float av = g_avg[k];
        a += av * logf(av + 1e-5f);
    }
    red[threadIdx.x] = a;
    __syncthreads();
    for (int s = 128; s; s >>= 1) {
        if (threadIdx.x < s) red[threadIdx.x] += red[threadIdx.x + s];
        __syncthreads();
    }
    if (threadIdx.x == 0) {
        float sample_entropy = -(g_sampleH / 8192.0f);
        float ent = 0.1f * (sample_entropy + red[0]);
        out[65536] = 1.25f * g_mse / 65536.0f + ent;
    }
}

// ---------------- launch ------------------------------------------------------
extern "C" void kernel_launch(void* const* d_in, const int* in_sizes, int n_in,
                              void* d_out, int out_size) {
    const float* z  = (const float*)d_in[0];
    const float* cb = (const float*)d_in[1];
    float* out = (float*)d_out;
    (void)in_sizes; (void)n_in; (void)out_size;

    k_init<<<64, 256>>>(cb);
    k_warm<<<128, 256>>>(z);
    k_nop<<<1, 32>>>();                       // keeps k_sweep as ncu's profiled launch
    k_sweep<<<dim3(K_CODES / CPB, RSPLIT), BT>>>(z);
    k_finalize<<<N_ROWS * 32 / 256, 256>>>(z, cb, out);
    k_final<<<1, 256>>>(out);
}